// round 15
// baseline (speedup 1.0000x reference)
#include <cuda_runtime.h>
#include <cuda_bf16.h>
#include <math.h>
#include <stdint.h>

// Problem constants
#define PN 2
#define PT 4096
#define PD 300
#define PH 6
#define PDH 50
#define PTOPK 20
#define NB (PH * PN)   // 12
#define NCAND 64
#define NQC 16         // rescue q-chunks (256 q rows each)
#define ZS 4           // scores q-split
#define KT 256         // keys per scores block
#define QCH 128        // q rows per chunk (scores)
#define RS 72          // smem row stride (bf16)

#define PST 24         // proj smem row stride (bf16)
#define KSTEPS 19      // ceil(300/16)
#define KCST 308       // candidate-K smem stride (floats)

typedef unsigned long long u64k;

// Scratch
__device__ __nv_bfloat16 g_Qh[(size_t)NB * PT * 64];   // [b][t][64], cols 50..63 stay 0
__device__ __nv_bfloat16 g_Qlo[(size_t)NB * PT * 64];  // bf16 residual of exact Q
__device__ __nv_bfloat16 g_Kh[(size_t)NB * PT * 64];
__device__ float g_maxapprox[ZS * NB * PT];
__device__ u64k  g_c1[NB * 1024];
__device__ int   g_cand[NB * NCAND];
__device__ float g_Kc[NB * NCAND * 52];                // exact candidate K rows
__device__ float g_exactpart[NB * NQC * NCAND];

// ---------------------------------------------------------------------------
// helpers
// ---------------------------------------------------------------------------
__device__ __forceinline__ uint32_t smem_u32(const void* p) {
    uint32_t a;
    asm("{ .reg .u64 t; cvta.to.shared.u64 t, %1; cvt.u32.u64 %0, t; }" : "=r"(a) : "l"(p));
    return a;
}

#define LDSM4(r, addr) \
    asm volatile("ldmatrix.sync.aligned.m8n8.x4.shared.b16 {%0,%1,%2,%3}, [%4];" \
                 : "=r"((r)[0]), "=r"((r)[1]), "=r"((r)[2]), "=r"((r)[3]) : "r"(addr))
#define LDSM2(r, addr) \
    asm volatile("ldmatrix.sync.aligned.m8n8.x2.shared.b16 {%0,%1}, [%2];" \
                 : "=r"((r)[0]), "=r"((r)[1]) : "r"(addr))

#define MMA16816(d, a, br0, br1) \
    asm volatile("mma.sync.aligned.m16n8k16.row.col.f32.bf16.bf16.f32 " \
                 "{%0,%1,%2,%3}, {%4,%5,%6,%7}, {%8,%9}, {%0,%1,%2,%3};" \
                 : "+f"((d)[0]), "+f"((d)[1]), "+f"((d)[2]), "+f"((d)[3]) \
                 : "r"((a)[0]), "r"((a)[1]), "r"((a)[2]), "r"((a)[3]), "r"(br0), "r"(br1))

#define CP_ASYNC16(dst, src) \
    asm volatile("cp.async.cg.shared.global [%0], [%1], 16;" :: "r"(dst), "l"(src))
#define CP_COMMIT() asm volatile("cp.async.commit_group;" ::: "memory")
#define CP_WAIT1()  asm volatile("cp.async.wait_group 1;" ::: "memory")

__device__ __forceinline__ uint32_t orderable(float v) {
    const uint32_t u = __float_as_uint(v);
    return (u & 0x80000000u) ? ~u : (u | 0x80000000u);
}

// ---------------------------------------------------------------------------
// Kernel 1: merged projections. grid (64, 4, 2).
// z=0: Q path, bf16x3 HMMA (fp32-accurate) -> g_Qh + g_Qlo.
// z=1: K path, single-bf16 HMMA (approx; scores only) -> g_Kh.
// ---------------------------------------------------------------------------
__global__ __launch_bounds__(256, 1) void proj_kernel(const float* __restrict__ Xq,
                                                      const float* __restrict__ Xk,
                                                      const float* __restrict__ Wq,
                                                      const float* __restrict__ Wk) {
    const bool qpath = (blockIdx.z == 0);
    const float* X = qpath ? Xq : Xk;
    const float* W = qpath ? Wq : Wk;

    const int m0 = blockIdx.x * 128;
    const int n0 = blockIdx.y * 80;

    __shared__ __align__(16) __nv_bfloat16 Xhi[128][PST];
    __shared__ __align__(16) __nv_bfloat16 Xlo[128][PST];
    __shared__ __align__(16) __nv_bfloat16 Whi[80][PST];
    __shared__ __align__(16) __nv_bfloat16 Wlo[80][PST];

    const int tid = threadIdx.x, w = tid >> 5, lane = tid & 31;
    const int wm = w >> 1, wn = w & 1;

    float acc[2][5][4];
#pragma unroll
    for (int mt = 0; mt < 2; ++mt)
#pragma unroll
        for (int nt = 0; nt < 5; ++nt)
#pragma unroll
            for (int j = 0; j < 4; ++j) acc[mt][nt][j] = 0.f;

    const uint32_t sxh = smem_u32(&Xhi[0][0]), sxl = smem_u32(&Xlo[0][0]);
    const uint32_t swh = smem_u32(&Whi[0][0]), swl = smem_u32(&Wlo[0][0]);

    for (int step = 0; step < KSTEPS; ++step) {
        const int k0 = step * 16;
        __syncthreads();
        for (int idx = tid; idx < 128 * 16; idx += 256) {
            const int r = idx >> 4, kk = idx & 15;
            const int k = k0 + kk;
            const float v = (k < PD) ? X[(size_t)(m0 + r) * PD + k] : 0.f;
            const __nv_bfloat16 h = __float2bfloat16_rn(v);
            Xhi[r][kk] = h;
            if (qpath) Xlo[r][kk] = __float2bfloat16_rn(v - __bfloat162float(h));
        }
        for (int idx = tid; idx < 80 * 16; idx += 256) {
            const int r = idx >> 4, kk = idx & 15;
            const int o = n0 + r, k = k0 + kk;
            const float v = (o < PD && k < PD) ? W[(size_t)o * PD + k] : 0.f;
            const __nv_bfloat16 h = __float2bfloat16_rn(v);
            Whi[r][kk] = h;
            if (qpath) Wlo[r][kk] = __float2bfloat16_rn(v - __bfloat162float(h));
        }
        __syncthreads();

        uint32_t ahi[2][4], alo[2][4];
        {
            const int r = lane & 15, ch = lane >> 4;
#pragma unroll
            for (int mt = 0; mt < 2; ++mt) {
                const uint32_t off = (uint32_t)(((wm * 32 + mt * 16 + r) * PST + ch * 8) * 2);
                LDSM4(ahi[mt], sxh + off);
                if (qpath) LDSM4(alo[mt], sxl + off);
            }
        }
        uint32_t bhi[5][2], blo[5][2];
        {
            const int sub = lane >> 3;
            const int nofs = (sub >> 1) * 8, kofs = (sub & 1) * 8;
#pragma unroll
            for (int p = 0; p < 2; ++p) {
                const int row = wn * 40 + p * 16 + nofs + (lane & 7);
                const uint32_t off = (uint32_t)((row * PST + kofs) * 2);
                uint32_t t[4];
                LDSM4(t, swh + off);
                bhi[2 * p][0] = t[0]; bhi[2 * p][1] = t[1];
                bhi[2 * p + 1][0] = t[2]; bhi[2 * p + 1][1] = t[3];
                if (qpath) {
                    LDSM4(t, swl + off);
                    blo[2 * p][0] = t[0]; blo[2 * p][1] = t[1];
                    blo[2 * p + 1][0] = t[2]; blo[2 * p + 1][1] = t[3];
                }
            }
            {
                const int row = wn * 40 + 32 + (lane & 7);
                const uint32_t off = (uint32_t)((row * PST + ((lane >> 3) & 1) * 8) * 2);
                LDSM2(bhi[4], swh + off);
                if (qpath) LDSM2(blo[4], swl + off);
            }
        }
        if (qpath) {
#pragma unroll
            for (int mt = 0; mt < 2; ++mt)
#pragma unroll
                for (int nt = 0; nt < 5; ++nt) {
                    MMA16816(acc[mt][nt], ahi[mt], bhi[nt][0], bhi[nt][1]);
                    MMA16816(acc[mt][nt], ahi[mt], blo[nt][0], blo[nt][1]);
                    MMA16816(acc[mt][nt], alo[mt], bhi[nt][0], bhi[nt][1]);
                }
        } else {
#pragma unroll
            for (int mt = 0; mt < 2; ++mt)
#pragma unroll
                for (int nt = 0; nt < 5; ++nt)
                    MMA16816(acc[mt][nt], ahi[mt], bhi[nt][0], bhi[nt][1]);
        }
    }

#pragma unroll
    for (int mt = 0; mt < 2; ++mt) {
        const int mbase = m0 + wm * 32 + mt * 16 + (lane >> 2);
#pragma unroll
        for (int nt = 0; nt < 5; ++nt) {
            const int obase = n0 + wn * 40 + nt * 8 + (lane & 3) * 2;
#pragma unroll
            for (int j = 0; j < 4; ++j) {
                const int m = mbase + (j >> 1) * 8;
                const int o = obase + (j & 1);
                if (o < PD) {
                    const float v = acc[mt][nt][j];
                    const int n = m >> 12, t = m & (PT - 1);
                    const int head = o / PDH, c = o - head * PDH;
                    const size_t idx = ((size_t)(head * PN + n) * PT + t) * 64 + c;
                    const __nv_bfloat16 h = __float2bfloat16_rn(v);
                    if (qpath) {
                        g_Qh[idx]  = h;
                        g_Qlo[idx] = __float2bfloat16_rn(v - __bfloat162float(h));
                    } else {
                        g_Kh[idx] = h;
                    }
                }
            }
        }
    }
}

// ---------------------------------------------------------------------------
// Kernel 2: approximate maxatt via warp-level bf16 HMMA. grid (16, 12, ZS=4).
// K=48 via 3 MMA ksteps + exact FFMA tail for dims 48,49 (dims 50..63 are 0).
// ---------------------------------------------------------------------------
__global__ __launch_bounds__(256, 1) void scores_mma_kernel() {
    extern __shared__ __align__(16) __nv_bfloat16 smq[];
    const int tid = threadIdx.x, w = tid >> 5, lane = tid & 31;
    const int kt = blockIdx.x, b = blockIdx.y, z = blockIdx.z;
    const uint32_t sq = smem_u32(smq);

    const __nv_bfloat16* Ktp = g_Kh + ((size_t)b * PT + kt * KT) * 64;
    for (int i = tid; i < KT * 8; i += 256) {
        const int row = i >> 3, ch = i & 7;
        *reinterpret_cast<float4*>(&smq[row * RS + ch * 8]) =
            *reinterpret_cast<const float4*>(Ktp + row * 64 + ch * 8);
    }
    __syncthreads();

    // A fragments: 3 ksteps (dims 0..47) + per-thread key-tail dims 48,49
    uint32_t a[2][3][4];
    float kt48[2][2], kt49[2][2];
    {
        const int r = lane & 15, ch = lane >> 4;
#pragma unroll
        for (int mt = 0; mt < 2; ++mt) {
            const uint32_t base = sq + (uint32_t)(((w * 32 + mt * 16 + r) * RS + ch * 8) * 2);
#pragma unroll
            for (int ks = 0; ks < 3; ++ks)
                LDSM4(a[mt][ks], base + ks * 32);
#pragma unroll
            for (int h = 0; h < 2; ++h) {
                const int row = w * 32 + mt * 16 + (lane >> 2) + h * 8;
                const __nv_bfloat162 kp =
                    *reinterpret_cast<const __nv_bfloat162*>(&smq[row * RS + 48]);
                kt48[mt][h] = __bfloat162float(kp.x);
                kt49[mt][h] = __bfloat162float(kp.y);
            }
        }
    }
    __syncthreads();

    const __nv_bfloat16* Qbp = g_Qh + ((size_t)b * PT + (size_t)z * (PT / ZS)) * 64;
    const int NCH = (PT / ZS) / QCH;   // 8

    {
        const __nv_bfloat16* src = Qbp;
        for (int i = tid; i < QCH * 8; i += 256) {
            const int row = i >> 3, ch = i & 7;
            CP_ASYNC16(sq + (uint32_t)((row * RS + ch * 8) * 2), src + row * 64 + ch * 8);
        }
        CP_COMMIT();
    }

    float rm[2][2] = { { -3.0e38f, -3.0e38f }, { -3.0e38f, -3.0e38f } };

    for (int c = 0; c < NCH; ++c) {
        if (c + 1 < NCH) {
            const uint32_t dst0 = sq + (uint32_t)(((c + 1) & 1) * QCH * RS * 2);
            const __nv_bfloat16* src = Qbp + (size_t)(c + 1) * QCH * 64;
            for (int i = tid; i < QCH * 8; i += 256) {
                const int row = i >> 3, ch = i & 7;
                CP_ASYNC16(dst0 + (uint32_t)((row * RS + ch * 8) * 2), src + row * 64 + ch * 8);
            }
        }
        CP_COMMIT();
        CP_WAIT1();
        __syncthreads();

        const uint32_t qbase = sq + (uint32_t)((c & 1) * QCH * RS * 2);
        const __nv_bfloat16* qsp = smq + (c & 1) * QCH * RS;
#pragma unroll 4
        for (int nt = 0; nt < 16; ++nt) {
            const uint32_t baddr =
                qbase + (uint32_t)(((nt * 8 + (lane & 7)) * RS + (lane >> 3) * 8) * 2);
            uint32_t bf0[4], bf1[4];
            LDSM4(bf0, baddr);        // ksteps 0,1 (dims 0..31)
            LDSM4(bf1, baddr + 64);   // ksteps 2,3 (dims 32..63); only [0],[1] used

            // q-tail dims 48,49 for this thread's two d columns
            const int qr0 = nt * 8 + 2 * (lane & 3);
            const __nv_bfloat162 qp0 =
                *reinterpret_cast<const __nv_bfloat162*>(&qsp[qr0 * RS + 48]);
            const __nv_bfloat162 qp1 =
                *reinterpret_cast<const __nv_bfloat162*>(&qsp[(qr0 + 1) * RS + 48]);
            const float q48a = __bfloat162float(qp0.x), q49a = __bfloat162float(qp0.y);
            const float q48b = __bfloat162float(qp1.x), q49b = __bfloat162float(qp1.y);

#pragma unroll
            for (int mt = 0; mt < 2; ++mt) {
                float d[4] = { 0.f, 0.f, 0.f, 0.f };
                MMA16816(d, a[mt][0], bf0[0], bf0[1]);
                MMA16816(d, a[mt][1], bf0[2], bf0[3]);
                MMA16816(d, a[mt][2], bf1[0], bf1[1]);
                d[0] += kt48[mt][0] * q48a + kt49[mt][0] * q49a;
                d[1] += kt48[mt][0] * q48b + kt49[mt][0] * q49b;
                d[2] += kt48[mt][1] * q48a + kt49[mt][1] * q49a;
                d[3] += kt48[mt][1] * q48b + kt49[mt][1] * q49b;
                rm[mt][0] = fmaxf(rm[mt][0], fmaxf(d[0], d[1]));
                rm[mt][1] = fmaxf(rm[mt][1], fmaxf(d[2], d[3]));
            }
        }
        __syncthreads();
    }

#pragma unroll
    for (int mt = 0; mt < 2; ++mt)
#pragma unroll
        for (int h = 0; h < 2; ++h) {
            rm[mt][h] = fmaxf(rm[mt][h], __shfl_xor_sync(0xffffffffu, rm[mt][h], 1));
            rm[mt][h] = fmaxf(rm[mt][h], __shfl_xor_sync(0xffffffffu, rm[mt][h], 2));
        }
    if ((lane & 3) == 0) {
        const size_t base = ((size_t)z * NB + b) * PT + kt * KT + w * 32;
#pragma unroll
        for (int mt = 0; mt < 2; ++mt) {
            g_maxapprox[base + mt * 16 + (lane >> 2)]     = rm[mt][0];
            g_maxapprox[base + mt * 16 + (lane >> 2) + 8] = rm[mt][1];
        }
    }
}

// ---------------------------------------------------------------------------
// Kernel 3a: per-slice bitonic sort (256 keys), emit slice top-64.
// grid (NB, 16) x 256. Folds ZS=4 partials.
// ---------------------------------------------------------------------------
__global__ __launch_bounds__(256) void cand_sortA_kernel() {
    const int b = blockIdx.x, sl = blockIdx.y, tid = threadIdx.x;
    __shared__ u64k key[256];

    const int i = sl * 256 + tid;
    float v = g_maxapprox[(size_t)b * PT + i];
#pragma unroll
    for (int zz = 1; zz < ZS; ++zz)
        v = fmaxf(v, g_maxapprox[((size_t)zz * NB + b) * PT + i]);
    key[tid] = ((u64k)orderable(v) << 32) | (uint32_t)(0xFFFFFFFFu - (uint32_t)i);
    __syncthreads();

#pragma unroll 1
    for (int k = 2; k <= 256; k <<= 1) {
#pragma unroll 1
        for (int j = k >> 1; j > 0; j >>= 1) {
            const int p = tid ^ j;
            const u64k mine = key[tid], other = key[p];
            const bool dirAsc = ((tid & k) != 0);
            const u64k nv = ((tid < p) == dirAsc)
                          ? (mine < other ? mine : other)
                          : (mine > other ? mine : other);
            __syncthreads();
            key[tid] = nv;
            __syncthreads();
        }
    }
    if (tid < 64) g_c1[(b * 16 + sl) * 64 + tid] = key[tid];
}

// ---------------------------------------------------------------------------
// Kernel 3b: bitonic sort of 1024 survivors; first 64 -> g_cand. grid NB x 1024.
// ---------------------------------------------------------------------------
__global__ __launch_bounds__(1024) void cand_sortB_kernel() {
    const int b = blockIdx.x, tid = threadIdx.x;
    __shared__ u64k key[1024];

    key[tid] = g_c1[b * 1024 + tid];
    __syncthreads();

#pragma unroll 1
    for (int k = 2; k <= 1024; k <<= 1) {
#pragma unroll 1
        for (int j = k >> 1; j > 0; j >>= 1) {
            const int p = tid ^ j;
            const u64k mine = key[tid], other = key[p];
            const bool dirAsc = ((tid & k) != 0);
            const u64k nv = ((tid < p) == dirAsc)
                          ? (mine < other ? mine : other)
                          : (mine > other ? mine : other);
            __syncthreads();
            key[tid] = nv;
            __syncthreads();
        }
    }
    if (tid < NCAND)
        g_cand[b * NCAND + tid] = (int)(0xFFFFFFFFu - (uint32_t)(key[tid] & 0xFFFFFFFFu));
}

// ---------------------------------------------------------------------------
// Kernel 3c: exact candidate-K gather-GEMM. grid (NB, 4) x 256; 16 cand/block.
// ---------------------------------------------------------------------------
__global__ __launch_bounds__(256) void kc_kernel(const float* __restrict__ keys,
                                                 const float* __restrict__ Wk) {
    const int b = blockIdx.x, g4 = blockIdx.y, tid = threadIdx.x;
    const int head = b / PN, n = b % PN;

    extern __shared__ __align__(16) float dsm[];
    float* sW    = dsm;              // [50][300]
    float* skeys = dsm + PDH * PD;   // [16][KCST]

    __shared__ int cid[16];
    if (tid < 16) cid[tid] = g_cand[b * NCAND + g4 * 16 + tid];
    __syncthreads();

    for (int i = tid; i < PDH * PD; i += 256)
        sW[i] = Wk[(size_t)(head * PDH) * PD + i];
    for (int i = tid; i < 16 * PD; i += 256) {
        const int c = i / PD, k = i - c * PD;
        skeys[c * KCST + k] = keys[((size_t)n * PT + cid[c]) * PD + k];
    }
    __syncthreads();

    const int c16 = tid & 15, jg = tid >> 4;
    float acc[4] = { 0.f, 0.f, 0.f, 0.f };

    for (int k = 0; k < PD; k += 4) {
        const float4 kv = *reinterpret_cast<const float4*>(&skeys[c16 * KCST + k]);
#pragma unroll
        for (int jj = 0; jj < 4; ++jj) {
            const int j = jg + 16 * jj;
            if (j < PDH) {
                const float4 wv4 = *reinterpret_cast<const float4*>(&sW[j * PD + k]);
                acc[jj] += kv.x * wv4.x + kv.y * wv4.y + kv.z * wv4.z + kv.w * wv4.w;
            }
        }
    }
#pragma unroll
    for (int jj = 0; jj < 4; ++jj) {
        const int j = jg + 16 * jj;
        if (j < PDH) g_Kc[(size_t)(b * NCAND + g4 * 16 + c16) * 52 + j] = acc[jj];
    }
}

// ---------------------------------------------------------------------------
// Kernel 4: per-candidate max over one 256-q chunk via bf16x3 HMMA
// (hi*hi + hi*lo + lo*hi). grid (NB, NQC=16) x 256.
// ---------------------------------------------------------------------------
__global__ __launch_bounds__(256, 1) void rescue_mma_kernel() {
    extern __shared__ __align__(16) __nv_bfloat16 rsm[];
    __nv_bfloat16* skhi = rsm;                       // [64][RS]
    __nv_bfloat16* sklo = rsm + 64 * RS;
    __nv_bfloat16* sqhi = rsm + 2 * 64 * RS;         // [256][RS]
    __nv_bfloat16* sqlo = rsm + 2 * 64 * RS + 256 * RS;

    __shared__ float sm_part[NCAND][8];

    const int b = blockIdx.x, qc = blockIdx.y;
    const int tid = threadIdx.x, w = tid >> 5, lane = tid & 31;
    const int q0 = qc * 256;

    for (int i = tid; i < 64 * 64; i += 256) {
        const int row = i >> 6, col = i & 63;
        const float v = (col < PDH) ? g_Kc[(size_t)(b * NCAND + row) * 52 + col] : 0.f;
        const __nv_bfloat16 h = __float2bfloat16_rn(v);
        skhi[row * RS + col] = h;
        sklo[row * RS + col] = __float2bfloat16_rn(v - __bfloat162float(h));
    }
    {
        const __nv_bfloat16* qh = g_Qh  + ((size_t)b * PT + q0) * 64;
        const __nv_bfloat16* ql = g_Qlo + ((size_t)b * PT + q0) * 64;
        for (int i = tid; i < 256 * 8; i += 256) {
            const int row = i >> 3, ch = i & 7;
            *reinterpret_cast<float4*>(&sqhi[row * RS + ch * 8]) =
                *reinterpret_cast<const float4*>(qh + row * 64 + ch * 8);
            *reinterpret_cast<float4*>(&sqlo[row * RS + ch * 8]) =
                *reinterpret_cast<const float4*>(ql + row * 64 + ch * 8);
        }
    }
    __syncthreads();

    const uint32_t skh = smem_u32(skhi), skl = smem_u32(sklo);
    const uint32_t sqh = smem_u32(sqhi), sql = smem_u32(sqlo);

    float rm[4][2];
#pragma unroll
    for (int mt = 0; mt < 4; ++mt) { rm[mt][0] = -3.0e38f; rm[mt][1] = -3.0e38f; }

#pragma unroll 1
    for (int mt = 0; mt < 4; ++mt) {
        uint32_t ahi[4][4], alo[4][4];
        {
            const int r = lane & 15, ch = lane >> 4;
            const uint32_t off = (uint32_t)(((mt * 16 + r) * RS + ch * 8) * 2);
#pragma unroll
            for (int ks = 0; ks < 4; ++ks) {
                LDSM4(ahi[ks], skh + off + ks * 32);
                LDSM4(alo[ks], skl + off + ks * 32);
            }
        }
#pragma unroll
        for (int nt = 0; nt < 4; ++nt) {
            const uint32_t boff =
                (uint32_t)(((w * 32 + nt * 8 + (lane & 7)) * RS + (lane >> 3) * 8) * 2);
            uint32_t bh0[4], bh1[4], bl0[4], bl1[4];
            LDSM4(bh0, sqh + boff);
            LDSM4(bh1, sqh + boff + 64);
            LDSM4(bl0, sql + boff);
            LDSM4(bl1, sql + boff + 64);

            float d[4] = { 0.f, 0.f, 0.f, 0.f };
            MMA16816(d, ahi[0], bh0[0], bh0[1]);
            MMA16816(d, ahi[1], bh0[2], bh0[3]);
            MMA16816(d, ahi[2], bh1[0], bh1[1]);
            MMA16816(d, ahi[3], bh1[2], bh1[3]);
            MMA16816(d, ahi[0], bl0[0], bl0[1]);
            MMA16816(d, ahi[1], bl0[2], bl0[3]);
            MMA16816(d, ahi[2], bl1[0], bl1[1]);
            MMA16816(d, ahi[3], bl1[2], bl1[3]);
            MMA16816(d, alo[0], bh0[0], bh0[1]);
            MMA16816(d, alo[1], bh0[2], bh0[3]);
            MMA16816(d, alo[2], bh1[0], bh1[1]);
            MMA16816(d, alo[3], bh1[2], bh1[3]);

            rm[mt][0] = fmaxf(rm[mt][0], fmaxf(d[0], d[1]));
            rm[mt][1] = fmaxf(rm[mt][1], fmaxf(d[2], d[3]));
        }
    }

#pragma unroll
    for (int mt = 0; mt < 4; ++mt)
#pragma unroll
        for (int h = 0; h < 2; ++h) {
            rm[mt][h] = fmaxf(rm[mt][h], __shfl_xor_sync(0xffffffffu, rm[mt][h], 1));
            rm[mt][h] = fmaxf(rm[mt][h], __shfl_xor_sync(0xffffffffu, rm[mt][h], 2));
        }
    if ((lane & 3) == 0) {
        const int r0 = lane >> 2;
#pragma unroll
        for (int mt = 0; mt < 4; ++mt) {
            sm_part[mt * 16 + r0][w]     = rm[mt][0];
            sm_part[mt * 16 + 8 + r0][w] = rm[mt][1];
        }
    }
    __syncthreads();
    if (tid < NCAND) {
        float m = sm_part[tid][0];
#pragma unroll
        for (int ww = 1; ww < 8; ++ww) m = fmaxf(m, sm_part[tid][ww]);
        g_exactpart[(size_t)(b * NQC + qc) * NCAND + tid] = m;
    }
}

// ---------------------------------------------------------------------------
// Kernel 5: fold chunks, top-20 (tie -> lowest global index), softmax,
// gather from g_Kc. grid 12 x 64.
// ---------------------------------------------------------------------------
__global__ __launch_bounds__(64) void final_kernel(float* __restrict__ out) {
    const int b = blockIdx.x;
    const int head = b / PN, n = b % PN;
    const int tid = threadIdx.x;

    __shared__ float w[NCAND];
    __shared__ int   ci[NCAND];
    __shared__ float bvs[NCAND];
    __shared__ int   bis[NCAND];
    __shared__ int   bss[NCAND];
    __shared__ float topv[PTOPK];
    __shared__ int   topslot[PTOPK];
    __shared__ int   winslot;
    __shared__ float probs[PTOPK];

    ci[tid] = g_cand[b * NCAND + tid];
    float e = -3.0e38f;
    for (int s = 0; s < NQC; ++s)
        e = fmaxf(e, g_exactpart[(size_t)(b * NQC + s) * NCAND + tid]);
    w[tid] = e;
    __syncthreads();

    for (int sel = 0; sel < PTOPK; ++sel) {
        bvs[tid] = w[tid]; bis[tid] = ci[tid]; bss[tid] = tid;
        __syncthreads();
        for (int s = 32; s; s >>= 1) {
            if (tid < s) {
                const float v2 = bvs[tid + s]; const int i2 = bis[tid + s];
                if (v2 > bvs[tid] || (v2 == bvs[tid] && i2 < bis[tid])) {
                    bvs[tid] = v2; bis[tid] = i2; bss[tid] = bss[tid + s];
                }
            }
            __syncthreads();
        }
        if (tid == 0) { topv[sel] = bvs[0]; topslot[sel] = bss[0]; winslot = bss[0]; }
        __syncthreads();
        if (tid == winslot) w[tid] = -3.0e38f;
        __syncthreads();
    }

    if (tid == 0) {
        const float inv = rsqrtf((float)PDH);
        float s = 0.f, ex[PTOPK];
#pragma unroll
        for (int i = 0; i < PTOPK; ++i) { ex[i] = expf((topv[i] - topv[0]) * inv); s += ex[i]; }
        const float invs = 1.0f / s;
#pragma unroll
        for (int i = 0; i < PTOPK; ++i) probs[i] = ex[i] * invs;
    }
    __syncthreads();

    for (int j = tid; j < PDH; j += 64) {
        float acc = 0.f;
#pragma unroll
        for (int i = 0; i < PTOPK; ++i)
            acc += probs[i] * g_Kc[(size_t)(b * NCAND + topslot[i]) * 52 + j];
        out[(size_t)n * PD + head * PDH + j] = acc;
    }
}

// ---------------------------------------------------------------------------
extern "C" void kernel_launch(void* const* d_in, const int* in_sizes, int n_in,
                              void* d_out, int out_size) {
    const float* querys = (const float*)d_in[0];
    const float* keys   = (const float*)d_in[1];
    const float* Wq     = (const float*)d_in[3];
    const float* Wk     = (const float*)d_in[4];

    dim3 gproj(PN * PT / 128, 4, 2);
    proj_kernel<<<gproj, 256>>>(querys, keys, Wq, Wk);

    const int scsmem = 2 * QCH * RS * 2;   // 36864 B
    dim3 gsc(PT / KT, NB, ZS);
    scores_mma_kernel<<<gsc, 256, scsmem>>>();

    cand_sortA_kernel<<<dim3(NB, 16), 256>>>();
    cand_sortB_kernel<<<NB, 1024>>>();

    const int kcsmem = (PDH * PD + 16 * KCST) * (int)sizeof(float);   // 79712 B
    cudaFuncSetAttribute(kc_kernel, cudaFuncAttributeMaxDynamicSharedMemorySize, kcsmem);
    kc_kernel<<<dim3(NB, 4), 256, kcsmem>>>(keys, Wk);

    const int rsmem = (2 * 64 * RS + 2 * 256 * RS) * 2;   // 92160 B
    cudaFuncSetAttribute(rescue_mma_kernel, cudaFuncAttributeMaxDynamicSharedMemorySize, rsmem);
    rescue_mma_kernel<<<dim3(NB, NQC), 256, rsmem>>>();

    final_kernel<<<NB, NCAND>>>((float*)d_out);
}

// round 16
// speedup vs baseline: 1.7341x; 1.7341x over previous
#include <cuda_runtime.h>
#include <cuda_bf16.h>
#include <math.h>
#include <stdint.h>

// Problem constants
#define PN 2
#define PT 4096
#define PD 300
#define PH 6
#define PDH 50
#define PTOPK 20
#define NB (PH * PN)   // 12
#define NCAND 64
#define NQC 16         // rescue q-chunks (256 q rows each)
#define ZS 4           // scores q-split
#define KT 256         // keys per scores block
#define QCH 128        // q rows per chunk (scores)
#define RS 72          // smem row stride (bf16)

#define PST 24         // proj smem row stride (bf16)
#define KSTEPS 19      // ceil(300/16)
#define KCST 308       // candidate-K smem stride (floats)

typedef unsigned long long u64k;

// Scratch
__device__ __nv_bfloat16 g_Qh[(size_t)NB * PT * 64];   // [b][t][64], cols 50..63 stay 0
__device__ __nv_bfloat16 g_Qlo[(size_t)NB * PT * 64];  // bf16 residual of exact Q
__device__ __nv_bfloat16 g_Kh[(size_t)NB * PT * 64];
__device__ float g_maxapprox[ZS * NB * PT];
__device__ u64k  g_c1[NB * 1024];
__device__ int   g_cand[NB * NCAND];
__device__ float g_Kc[NB * NCAND * 52];                // exact candidate K rows
__device__ float g_exactpart[NB * NQC * NCAND];

// ---------------------------------------------------------------------------
// helpers
// ---------------------------------------------------------------------------
__device__ __forceinline__ uint32_t smem_u32(const void* p) {
    uint32_t a;
    asm("{ .reg .u64 t; cvta.to.shared.u64 t, %1; cvt.u32.u64 %0, t; }" : "=r"(a) : "l"(p));
    return a;
}

#define LDSM4(r, addr) \
    asm volatile("ldmatrix.sync.aligned.m8n8.x4.shared.b16 {%0,%1,%2,%3}, [%4];" \
                 : "=r"((r)[0]), "=r"((r)[1]), "=r"((r)[2]), "=r"((r)[3]) : "r"(addr))
#define LDSM2(r, addr) \
    asm volatile("ldmatrix.sync.aligned.m8n8.x2.shared.b16 {%0,%1}, [%2];" \
                 : "=r"((r)[0]), "=r"((r)[1]) : "r"(addr))

#define MMA16816(d, a, br0, br1) \
    asm volatile("mma.sync.aligned.m16n8k16.row.col.f32.bf16.bf16.f32 " \
                 "{%0,%1,%2,%3}, {%4,%5,%6,%7}, {%8,%9}, {%0,%1,%2,%3};" \
                 : "+f"((d)[0]), "+f"((d)[1]), "+f"((d)[2]), "+f"((d)[3]) \
                 : "r"((a)[0]), "r"((a)[1]), "r"((a)[2]), "r"((a)[3]), "r"(br0), "r"(br1))

#define CP_ASYNC16(dst, src) \
    asm volatile("cp.async.cg.shared.global [%0], [%1], 16;" :: "r"(dst), "l"(src))
#define CP_COMMIT() asm volatile("cp.async.commit_group;" ::: "memory")
#define CP_WAIT1()  asm volatile("cp.async.wait_group 1;" ::: "memory")

__device__ __forceinline__ uint32_t orderable(float v) {
    const uint32_t u = __float_as_uint(v);
    return (u & 0x80000000u) ? ~u : (u | 0x80000000u);
}

// ---------------------------------------------------------------------------
// Kernel 1: merged projections. grid (64, 4, 2).
// z=0: Q path, bf16x3 HMMA (fp32-accurate) -> g_Qh + g_Qlo.
// z=1: K path, single-bf16 HMMA (approx; scores only) -> g_Kh.
// ---------------------------------------------------------------------------
__global__ __launch_bounds__(256, 1) void proj_kernel(const float* __restrict__ Xq,
                                                      const float* __restrict__ Xk,
                                                      const float* __restrict__ Wq,
                                                      const float* __restrict__ Wk) {
    const bool qpath = (blockIdx.z == 0);
    const float* X = qpath ? Xq : Xk;
    const float* W = qpath ? Wq : Wk;

    const int m0 = blockIdx.x * 128;
    const int n0 = blockIdx.y * 80;

    __shared__ __align__(16) __nv_bfloat16 Xhi[128][PST];
    __shared__ __align__(16) __nv_bfloat16 Xlo[128][PST];
    __shared__ __align__(16) __nv_bfloat16 Whi[80][PST];
    __shared__ __align__(16) __nv_bfloat16 Wlo[80][PST];

    const int tid = threadIdx.x, w = tid >> 5, lane = tid & 31;
    const int wm = w >> 1, wn = w & 1;

    float acc[2][5][4];
#pragma unroll
    for (int mt = 0; mt < 2; ++mt)
#pragma unroll
        for (int nt = 0; nt < 5; ++nt)
#pragma unroll
            for (int j = 0; j < 4; ++j) acc[mt][nt][j] = 0.f;

    const uint32_t sxh = smem_u32(&Xhi[0][0]), sxl = smem_u32(&Xlo[0][0]);
    const uint32_t swh = smem_u32(&Whi[0][0]), swl = smem_u32(&Wlo[0][0]);

    for (int step = 0; step < KSTEPS; ++step) {
        const int k0 = step * 16;
        __syncthreads();
        for (int idx = tid; idx < 128 * 16; idx += 256) {
            const int r = idx >> 4, kk = idx & 15;
            const int k = k0 + kk;
            const float v = (k < PD) ? X[(size_t)(m0 + r) * PD + k] : 0.f;
            const __nv_bfloat16 h = __float2bfloat16_rn(v);
            Xhi[r][kk] = h;
            if (qpath) Xlo[r][kk] = __float2bfloat16_rn(v - __bfloat162float(h));
        }
        for (int idx = tid; idx < 80 * 16; idx += 256) {
            const int r = idx >> 4, kk = idx & 15;
            const int o = n0 + r, k = k0 + kk;
            const float v = (o < PD && k < PD) ? W[(size_t)o * PD + k] : 0.f;
            const __nv_bfloat16 h = __float2bfloat16_rn(v);
            Whi[r][kk] = h;
            if (qpath) Wlo[r][kk] = __float2bfloat16_rn(v - __bfloat162float(h));
        }
        __syncthreads();

        uint32_t ahi[2][4], alo[2][4];
        {
            const int r = lane & 15, ch = lane >> 4;
#pragma unroll
            for (int mt = 0; mt < 2; ++mt) {
                const uint32_t off = (uint32_t)(((wm * 32 + mt * 16 + r) * PST + ch * 8) * 2);
                LDSM4(ahi[mt], sxh + off);
                if (qpath) LDSM4(alo[mt], sxl + off);
            }
        }
        uint32_t bhi[5][2], blo[5][2];
        {
            const int sub = lane >> 3;
            const int nofs = (sub >> 1) * 8, kofs = (sub & 1) * 8;
#pragma unroll
            for (int p = 0; p < 2; ++p) {
                const int row = wn * 40 + p * 16 + nofs + (lane & 7);
                const uint32_t off = (uint32_t)((row * PST + kofs) * 2);
                uint32_t t[4];
                LDSM4(t, swh + off);
                bhi[2 * p][0] = t[0]; bhi[2 * p][1] = t[1];
                bhi[2 * p + 1][0] = t[2]; bhi[2 * p + 1][1] = t[3];
                if (qpath) {
                    LDSM4(t, swl + off);
                    blo[2 * p][0] = t[0]; blo[2 * p][1] = t[1];
                    blo[2 * p + 1][0] = t[2]; blo[2 * p + 1][1] = t[3];
                }
            }
            {
                const int row = wn * 40 + 32 + (lane & 7);
                const uint32_t off = (uint32_t)((row * PST + ((lane >> 3) & 1) * 8) * 2);
                LDSM2(bhi[4], swh + off);
                if (qpath) LDSM2(blo[4], swl + off);
            }
        }
        if (qpath) {
#pragma unroll
            for (int mt = 0; mt < 2; ++mt)
#pragma unroll
                for (int nt = 0; nt < 5; ++nt) {
                    MMA16816(acc[mt][nt], ahi[mt], bhi[nt][0], bhi[nt][1]);
                    MMA16816(acc[mt][nt], ahi[mt], blo[nt][0], blo[nt][1]);
                    MMA16816(acc[mt][nt], alo[mt], bhi[nt][0], bhi[nt][1]);
                }
        } else {
#pragma unroll
            for (int mt = 0; mt < 2; ++mt)
#pragma unroll
                for (int nt = 0; nt < 5; ++nt)
                    MMA16816(acc[mt][nt], ahi[mt], bhi[nt][0], bhi[nt][1]);
        }
    }

#pragma unroll
    for (int mt = 0; mt < 2; ++mt) {
        const int mbase = m0 + wm * 32 + mt * 16 + (lane >> 2);
#pragma unroll
        for (int nt = 0; nt < 5; ++nt) {
            const int obase = n0 + wn * 40 + nt * 8 + (lane & 3) * 2;
#pragma unroll
            for (int j = 0; j < 4; ++j) {
                const int m = mbase + (j >> 1) * 8;
                const int o = obase + (j & 1);
                if (o < PD) {
                    const float v = acc[mt][nt][j];
                    const int n = m >> 12, t = m & (PT - 1);
                    const int head = o / PDH, c = o - head * PDH;
                    const size_t idx = ((size_t)(head * PN + n) * PT + t) * 64 + c;
                    const __nv_bfloat16 h = __float2bfloat16_rn(v);
                    if (qpath) {
                        g_Qh[idx]  = h;
                        g_Qlo[idx] = __float2bfloat16_rn(v - __bfloat162float(h));
                    } else {
                        g_Kh[idx] = h;
                    }
                }
            }
        }
    }
}

// ---------------------------------------------------------------------------
// Kernel 2: approximate maxatt via warp-level bf16 HMMA. grid (16, 12, ZS=4).
// (R14 proven version — do not touch the inner loop.)
// ---------------------------------------------------------------------------
__global__ __launch_bounds__(256, 1) void scores_mma_kernel() {
    extern __shared__ __align__(16) __nv_bfloat16 smq[];
    const int tid = threadIdx.x, w = tid >> 5, lane = tid & 31;
    const int kt = blockIdx.x, b = blockIdx.y, z = blockIdx.z;
    const uint32_t sq = smem_u32(smq);

    const __nv_bfloat16* Ktp = g_Kh + ((size_t)b * PT + kt * KT) * 64;
    for (int i = tid; i < KT * 8; i += 256) {
        const int row = i >> 3, ch = i & 7;
        *reinterpret_cast<float4*>(&smq[row * RS + ch * 8]) =
            *reinterpret_cast<const float4*>(Ktp + row * 64 + ch * 8);
    }
    __syncthreads();

    uint32_t a[2][4][4];
    {
        const int r = lane & 15, ch = lane >> 4;
#pragma unroll
        for (int mt = 0; mt < 2; ++mt) {
            const uint32_t base = sq + (uint32_t)(((w * 32 + mt * 16 + r) * RS + ch * 8) * 2);
#pragma unroll
            for (int ks = 0; ks < 4; ++ks)
                LDSM4(a[mt][ks], base + ks * 32);
        }
    }
    __syncthreads();

    const __nv_bfloat16* Qbp = g_Qh + ((size_t)b * PT + (size_t)z * (PT / ZS)) * 64;
    const int NCH = (PT / ZS) / QCH;   // 8

    {
        const __nv_bfloat16* src = Qbp;
        for (int i = tid; i < QCH * 8; i += 256) {
            const int row = i >> 3, ch = i & 7;
            CP_ASYNC16(sq + (uint32_t)((row * RS + ch * 8) * 2), src + row * 64 + ch * 8);
        }
        CP_COMMIT();
    }

    float rm[2][2] = { { -3.0e38f, -3.0e38f }, { -3.0e38f, -3.0e38f } };

    for (int c = 0; c < NCH; ++c) {
        if (c + 1 < NCH) {
            const uint32_t dst0 = sq + (uint32_t)(((c + 1) & 1) * QCH * RS * 2);
            const __nv_bfloat16* src = Qbp + (size_t)(c + 1) * QCH * 64;
            for (int i = tid; i < QCH * 8; i += 256) {
                const int row = i >> 3, ch = i & 7;
                CP_ASYNC16(dst0 + (uint32_t)((row * RS + ch * 8) * 2), src + row * 64 + ch * 8);
            }
        }
        CP_COMMIT();
        CP_WAIT1();
        __syncthreads();

        const uint32_t qbase = sq + (uint32_t)((c & 1) * QCH * RS * 2);
#pragma unroll 4
        for (int nt = 0; nt < 16; ++nt) {
            const uint32_t baddr =
                qbase + (uint32_t)(((nt * 8 + (lane & 7)) * RS + (lane >> 3) * 8) * 2);
            uint32_t bf0[4], bf1[4];
            LDSM4(bf0, baddr);
            LDSM4(bf1, baddr + 64);
#pragma unroll
            for (int mt = 0; mt < 2; ++mt) {
                float d[4] = { 0.f, 0.f, 0.f, 0.f };
                MMA16816(d, a[mt][0], bf0[0], bf0[1]);
                MMA16816(d, a[mt][1], bf0[2], bf0[3]);
                MMA16816(d, a[mt][2], bf1[0], bf1[1]);
                MMA16816(d, a[mt][3], bf1[2], bf1[3]);
                rm[mt][0] = fmaxf(rm[mt][0], fmaxf(d[0], d[1]));
                rm[mt][1] = fmaxf(rm[mt][1], fmaxf(d[2], d[3]));
            }
        }
        __syncthreads();
    }

#pragma unroll
    for (int mt = 0; mt < 2; ++mt)
#pragma unroll
        for (int h = 0; h < 2; ++h) {
            rm[mt][h] = fmaxf(rm[mt][h], __shfl_xor_sync(0xffffffffu, rm[mt][h], 1));
            rm[mt][h] = fmaxf(rm[mt][h], __shfl_xor_sync(0xffffffffu, rm[mt][h], 2));
        }
    if ((lane & 3) == 0) {
        const size_t base = ((size_t)z * NB + b) * PT + kt * KT + w * 32;
#pragma unroll
        for (int mt = 0; mt < 2; ++mt) {
            g_maxapprox[base + mt * 16 + (lane >> 2)]     = rm[mt][0];
            g_maxapprox[base + mt * 16 + (lane >> 2) + 8] = rm[mt][1];
        }
    }
}

// ---------------------------------------------------------------------------
// Kernel 3a: per-slice bitonic sort (256 keys), emit slice top-64.
// grid (NB, 16) x 256. Folds ZS=4 partials.
// ---------------------------------------------------------------------------
__global__ __launch_bounds__(256) void cand_sortA_kernel() {
    const int b = blockIdx.x, sl = blockIdx.y, tid = threadIdx.x;
    __shared__ u64k key[256];

    const int i = sl * 256 + tid;
    float v = g_maxapprox[(size_t)b * PT + i];
#pragma unroll
    for (int zz = 1; zz < ZS; ++zz)
        v = fmaxf(v, g_maxapprox[((size_t)zz * NB + b) * PT + i]);
    key[tid] = ((u64k)orderable(v) << 32) | (uint32_t)(0xFFFFFFFFu - (uint32_t)i);
    __syncthreads();

#pragma unroll 1
    for (int k = 2; k <= 256; k <<= 1) {
#pragma unroll 1
        for (int j = k >> 1; j > 0; j >>= 1) {
            const int p = tid ^ j;
            const u64k mine = key[tid], other = key[p];
            const bool dirAsc = ((tid & k) != 0);
            const u64k nv = ((tid < p) == dirAsc)
                          ? (mine < other ? mine : other)
                          : (mine > other ? mine : other);
            __syncthreads();
            key[tid] = nv;
            __syncthreads();
        }
    }
    if (tid < 64) g_c1[(b * 16 + sl) * 64 + tid] = key[tid];
}

// ---------------------------------------------------------------------------
// Kernel 3b: bitonic sort of 1024 survivors; first 64 -> g_cand. grid NB x 1024.
// ---------------------------------------------------------------------------
__global__ __launch_bounds__(1024) void cand_sortB_kernel() {
    const int b = blockIdx.x, tid = threadIdx.x;
    __shared__ u64k key[1024];

    key[tid] = g_c1[b * 1024 + tid];
    __syncthreads();

#pragma unroll 1
    for (int k = 2; k <= 1024; k <<= 1) {
#pragma unroll 1
        for (int j = k >> 1; j > 0; j >>= 1) {
            const int p = tid ^ j;
            const u64k mine = key[tid], other = key[p];
            const bool dirAsc = ((tid & k) != 0);
            const u64k nv = ((tid < p) == dirAsc)
                          ? (mine < other ? mine : other)
                          : (mine > other ? mine : other);
            __syncthreads();
            key[tid] = nv;
            __syncthreads();
        }
    }
    if (tid < NCAND)
        g_cand[b * NCAND + tid] = (int)(0xFFFFFFFFu - (uint32_t)(key[tid] & 0xFFFFFFFFu));
}

// ---------------------------------------------------------------------------
// Kernel 3c: exact candidate-K gather-GEMM. grid (NB, 4) x 256; 16 cand/block.
// ---------------------------------------------------------------------------
__global__ __launch_bounds__(256) void kc_kernel(const float* __restrict__ keys,
                                                 const float* __restrict__ Wk) {
    const int b = blockIdx.x, g4 = blockIdx.y, tid = threadIdx.x;
    const int head = b / PN, n = b % PN;

    extern __shared__ __align__(16) float dsm[];
    float* sW    = dsm;              // [50][300]
    float* skeys = dsm + PDH * PD;   // [16][KCST]

    __shared__ int cid[16];
    if (tid < 16) cid[tid] = g_cand[b * NCAND + g4 * 16 + tid];
    __syncthreads();

    for (int i = tid; i < PDH * PD; i += 256)
        sW[i] = Wk[(size_t)(head * PDH) * PD + i];
    for (int i = tid; i < 16 * PD; i += 256) {
        const int c = i / PD, k = i - c * PD;
        skeys[c * KCST + k] = keys[((size_t)n * PT + cid[c]) * PD + k];
    }
    __syncthreads();

    const int c16 = tid & 15, jg = tid >> 4;
    float acc[4] = { 0.f, 0.f, 0.f, 0.f };

    for (int k = 0; k < PD; k += 4) {
        const float4 kv = *reinterpret_cast<const float4*>(&skeys[c16 * KCST + k]);
#pragma unroll
        for (int jj = 0; jj < 4; ++jj) {
            const int j = jg + 16 * jj;
            if (j < PDH) {
                const float4 wv4 = *reinterpret_cast<const float4*>(&sW[j * PD + k]);
                acc[jj] += kv.x * wv4.x + kv.y * wv4.y + kv.z * wv4.z + kv.w * wv4.w;
            }
        }
    }
#pragma unroll
    for (int jj = 0; jj < 4; ++jj) {
        const int j = jg + 16 * jj;
        if (j < PDH) g_Kc[(size_t)(b * NCAND + g4 * 16 + c16) * 52 + j] = acc[jj];
    }
}

// ---------------------------------------------------------------------------
// Kernel 4: per-candidate max over one 256-q chunk via bf16x3 HMMA
// (hi*hi + hi*lo + lo*hi). grid (NB, NQC=16) x 256.
// ---------------------------------------------------------------------------
__global__ __launch_bounds__(256, 1) void rescue_mma_kernel() {
    extern __shared__ __align__(16) __nv_bfloat16 rsm[];
    __nv_bfloat16* skhi = rsm;                       // [64][RS]
    __nv_bfloat16* sklo = rsm + 64 * RS;
    __nv_bfloat16* sqhi = rsm + 2 * 64 * RS;         // [256][RS]
    __nv_bfloat16* sqlo = rsm + 2 * 64 * RS + 256 * RS;

    __shared__ float sm_part[NCAND][8];

    const int b = blockIdx.x, qc = blockIdx.y;
    const int tid = threadIdx.x, w = tid >> 5, lane = tid & 31;
    const int q0 = qc * 256;

    for (int i = tid; i < 64 * 64; i += 256) {
        const int row = i >> 6, col = i & 63;
        const float v = (col < PDH) ? g_Kc[(size_t)(b * NCAND + row) * 52 + col] : 0.f;
        const __nv_bfloat16 h = __float2bfloat16_rn(v);
        skhi[row * RS + col] = h;
        sklo[row * RS + col] = __float2bfloat16_rn(v - __bfloat162float(h));
    }
    {
        const __nv_bfloat16* qh = g_Qh  + ((size_t)b * PT + q0) * 64;
        const __nv_bfloat16* ql = g_Qlo + ((size_t)b * PT + q0) * 64;
        for (int i = tid; i < 256 * 8; i += 256) {
            const int row = i >> 3, ch = i & 7;
            *reinterpret_cast<float4*>(&sqhi[row * RS + ch * 8]) =
                *reinterpret_cast<const float4*>(qh + row * 64 + ch * 8);
            *reinterpret_cast<float4*>(&sqlo[row * RS + ch * 8]) =
                *reinterpret_cast<const float4*>(ql + row * 64 + ch * 8);
        }
    }
    __syncthreads();

    const uint32_t skh = smem_u32(skhi), skl = smem_u32(sklo);
    const uint32_t sqh = smem_u32(sqhi), sql = smem_u32(sqlo);

    float rm[4][2];
#pragma unroll
    for (int mt = 0; mt < 4; ++mt) { rm[mt][0] = -3.0e38f; rm[mt][1] = -3.0e38f; }

#pragma unroll 1
    for (int mt = 0; mt < 4; ++mt) {
        uint32_t ahi[4][4], alo[4][4];
        {
            const int r = lane & 15, ch = lane >> 4;
            const uint32_t off = (uint32_t)(((mt * 16 + r) * RS + ch * 8) * 2);
#pragma unroll
            for (int ks = 0; ks < 4; ++ks) {
                LDSM4(ahi[ks], skh + off + ks * 32);
                LDSM4(alo[ks], skl + off + ks * 32);
            }
        }
#pragma unroll
        for (int nt = 0; nt < 4; ++nt) {
            const uint32_t boff =
                (uint32_t)(((w * 32 + nt * 8 + (lane & 7)) * RS + (lane >> 3) * 8) * 2);
            uint32_t bh0[4], bh1[4], bl0[4], bl1[4];
            LDSM4(bh0, sqh + boff);
            LDSM4(bh1, sqh + boff + 64);
            LDSM4(bl0, sql + boff);
            LDSM4(bl1, sql + boff + 64);

            float d[4] = { 0.f, 0.f, 0.f, 0.f };
            MMA16816(d, ahi[0], bh0[0], bh0[1]);
            MMA16816(d, ahi[1], bh0[2], bh0[3]);
            MMA16816(d, ahi[2], bh1[0], bh1[1]);
            MMA16816(d, ahi[3], bh1[2], bh1[3]);
            MMA16816(d, ahi[0], bl0[0], bl0[1]);
            MMA16816(d, ahi[1], bl0[2], bl0[3]);
            MMA16816(d, ahi[2], bl1[0], bl1[1]);
            MMA16816(d, ahi[3], bl1[2], bl1[3]);
            MMA16816(d, alo[0], bh0[0], bh0[1]);
            MMA16816(d, alo[1], bh0[2], bh0[3]);
            MMA16816(d, alo[2], bh1[0], bh1[1]);
            MMA16816(d, alo[3], bh1[2], bh1[3]);

            rm[mt][0] = fmaxf(rm[mt][0], fmaxf(d[0], d[1]));
            rm[mt][1] = fmaxf(rm[mt][1], fmaxf(d[2], d[3]));
        }
    }

#pragma unroll
    for (int mt = 0; mt < 4; ++mt)
#pragma unroll
        for (int h = 0; h < 2; ++h) {
            rm[mt][h] = fmaxf(rm[mt][h], __shfl_xor_sync(0xffffffffu, rm[mt][h], 1));
            rm[mt][h] = fmaxf(rm[mt][h], __shfl_xor_sync(0xffffffffu, rm[mt][h], 2));
        }
    if ((lane & 3) == 0) {
        const int r0 = lane >> 2;
#pragma unroll
        for (int mt = 0; mt < 4; ++mt) {
            sm_part[mt * 16 + r0][w]     = rm[mt][0];
            sm_part[mt * 16 + 8 + r0][w] = rm[mt][1];
        }
    }
    __syncthreads();
    if (tid < NCAND) {
        float m = sm_part[tid][0];
#pragma unroll
        for (int ww = 1; ww < 8; ++ww) m = fmaxf(m, sm_part[tid][ww]);
        g_exactpart[(size_t)(b * NQC + qc) * NCAND + tid] = m;
    }
}

// ---------------------------------------------------------------------------
// Kernel 5: fold chunks, single-pass rank top-20 (value desc, tie -> lowest
// global index), softmax, gather from g_Kc. grid 12 x 64.
// ---------------------------------------------------------------------------
__global__ __launch_bounds__(64) void final_kernel(float* __restrict__ out) {
    const int b = blockIdx.x;
    const int head = b / PN, n = b % PN;
    const int tid = threadIdx.x;

    __shared__ u64k  keys_s[NCAND];
    __shared__ float topv[PTOPK];
    __shared__ int   topslot[PTOPK];
    __shared__ float probs[PTOPK];

    const int ci = g_cand[b * NCAND + tid];
    float e = -3.0e38f;
    for (int s = 0; s < NQC; ++s)
        e = fmaxf(e, g_exactpart[(size_t)(b * NQC + s) * NCAND + tid]);

    // unique total order: value desc, then global index asc
    const u64k mine = ((u64k)orderable(e) << 32) | (uint32_t)(0xFFFFFFFFu - (uint32_t)ci);
    keys_s[tid] = mine;
    __syncthreads();

    int rank = 0;
#pragma unroll
    for (int j = 0; j < NCAND; ++j)
        rank += (keys_s[j] > mine);

    if (rank < PTOPK) { topv[rank] = e; topslot[rank] = tid; }
    __syncthreads();

    if (tid == 0) {
        const float inv = rsqrtf((float)PDH);
        float s = 0.f, ex[PTOPK];
#pragma unroll
        for (int i = 0; i < PTOPK; ++i) { ex[i] = expf((topv[i] - topv[0]) * inv); s += ex[i]; }
        const float invs = 1.0f / s;
#pragma unroll
        for (int i = 0; i < PTOPK; ++i) probs[i] = ex[i] * invs;
    }
    __syncthreads();

    for (int j = tid; j < PDH; j += 64) {
        float acc = 0.f;
#pragma unroll
        for (int i = 0; i < PTOPK; ++i)
            acc += probs[i] * g_Kc[(size_t)(b * NCAND + topslot[i]) * 52 + j];
        out[(size_t)n * PD + head * PDH + j] = acc;
    }
}

// ---------------------------------------------------------------------------
extern "C" void kernel_launch(void* const* d_in, const int* in_sizes, int n_in,
                              void* d_out, int out_size) {
    const float* querys = (const float*)d_in[0];
    const float* keys   = (const float*)d_in[1];
    const float* Wq     = (const float*)d_in[3];
    const float* Wk     = (const float*)d_in[4];

    dim3 gproj(PN * PT / 128, 4, 2);
    proj_kernel<<<gproj, 256>>>(querys, keys, Wq, Wk);

    const int scsmem = 2 * QCH * RS * 2;   // 36864 B
    dim3 gsc(PT / KT, NB, ZS);
    scores_mma_kernel<<<gsc, 256, scsmem>>>();

    cand_sortA_kernel<<<dim3(NB, 16), 256>>>();
    cand_sortB_kernel<<<NB, 1024>>>();

    const int kcsmem = (PDH * PD + 16 * KCST) * (int)sizeof(float);   // 79712 B
    cudaFuncSetAttribute(kc_kernel, cudaFuncAttributeMaxDynamicSharedMemorySize, kcsmem);
    kc_kernel<<<dim3(NB, 4), 256, kcsmem>>>(keys, Wk);

    const int rsmem = (2 * 64 * RS + 2 * 256 * RS) * 2;   // 92160 B
    cudaFuncSetAttribute(rescue_mma_kernel, cudaFuncAttributeMaxDynamicSharedMemorySize, rsmem);
    rescue_mma_kernel<<<dim3(NB, NQC), 256, rsmem>>>();

    final_kernel<<<NB, NCAND>>>((float*)d_out);
}

// round 17
// speedup vs baseline: 1.7514x; 1.0100x over previous
#include <cuda_runtime.h>
#include <cuda_bf16.h>
#include <math.h>
#include <stdint.h>

// Problem constants
#define PN 2
#define PT 4096
#define PD 300
#define PH 6
#define PDH 50
#define PTOPK 20
#define NB (PH * PN)   // 12
#define NCAND 64
#define NQC 16         // rescue q-chunks (256 q rows each)
#define ZS 8           // scores q-split
#define KT 256         // keys per scores block
#define QCH 128        // q rows per chunk (scores)
#define RS 72          // smem row stride (bf16)

#define PST 24         // proj smem row stride (bf16)
#define KSTEPS 19      // ceil(300/16)
#define KCST 308       // candidate-K smem stride (floats)

typedef unsigned long long u64k;

// Scratch
__device__ __nv_bfloat16 g_Qh[(size_t)NB * PT * 64];   // [b][t][64], cols 50..63 stay 0
__device__ __nv_bfloat16 g_Qlo[(size_t)NB * PT * 64];  // bf16 residual of exact Q
__device__ __nv_bfloat16 g_Kh[(size_t)NB * PT * 64];
__device__ float g_maxapprox[ZS * NB * PT];
__device__ u64k  g_c1[NB * 1024];
__device__ int   g_cand[NB * NCAND];
__device__ float g_Kc[NB * NCAND * 52];                // exact candidate K rows
__device__ float g_exactpart[NB * NQC * NCAND];

// ---------------------------------------------------------------------------
// helpers
// ---------------------------------------------------------------------------
__device__ __forceinline__ uint32_t smem_u32(const void* p) {
    uint32_t a;
    asm("{ .reg .u64 t; cvta.to.shared.u64 t, %1; cvt.u32.u64 %0, t; }" : "=r"(a) : "l"(p));
    return a;
}

#define LDSM4(r, addr) \
    asm volatile("ldmatrix.sync.aligned.m8n8.x4.shared.b16 {%0,%1,%2,%3}, [%4];" \
                 : "=r"((r)[0]), "=r"((r)[1]), "=r"((r)[2]), "=r"((r)[3]) : "r"(addr))
#define LDSM2(r, addr) \
    asm volatile("ldmatrix.sync.aligned.m8n8.x2.shared.b16 {%0,%1}, [%2];" \
                 : "=r"((r)[0]), "=r"((r)[1]) : "r"(addr))

#define MMA16816(d, a, br0, br1) \
    asm volatile("mma.sync.aligned.m16n8k16.row.col.f32.bf16.bf16.f32 " \
                 "{%0,%1,%2,%3}, {%4,%5,%6,%7}, {%8,%9}, {%0,%1,%2,%3};" \
                 : "+f"((d)[0]), "+f"((d)[1]), "+f"((d)[2]), "+f"((d)[3]) \
                 : "r"((a)[0]), "r"((a)[1]), "r"((a)[2]), "r"((a)[3]), "r"(br0), "r"(br1))

#define CP_ASYNC16(dst, src) \
    asm volatile("cp.async.cg.shared.global [%0], [%1], 16;" :: "r"(dst), "l"(src))
#define CP_COMMIT() asm volatile("cp.async.commit_group;" ::: "memory")
#define CP_WAIT1()  asm volatile("cp.async.wait_group 1;" ::: "memory")

__device__ __forceinline__ uint32_t orderable(float v) {
    const uint32_t u = __float_as_uint(v);
    return (u & 0x80000000u) ? ~u : (u | 0x80000000u);
}

// ---------------------------------------------------------------------------
// Kernel 1: merged projections. grid (64, 4, 2).
// z=0: Q path, bf16x3 HMMA (fp32-accurate) -> g_Qh + g_Qlo.
// z=1: K path, single-bf16 HMMA (approx; scores only) -> g_Kh.
// ---------------------------------------------------------------------------
__global__ __launch_bounds__(256, 1) void proj_kernel(const float* __restrict__ Xq,
                                                      const float* __restrict__ Xk,
                                                      const float* __restrict__ Wq,
                                                      const float* __restrict__ Wk) {
    const bool qpath = (blockIdx.z == 0);
    const float* X = qpath ? Xq : Xk;
    const float* W = qpath ? Wq : Wk;

    const int m0 = blockIdx.x * 128;
    const int n0 = blockIdx.y * 80;

    __shared__ __align__(16) __nv_bfloat16 Xhi[128][PST];
    __shared__ __align__(16) __nv_bfloat16 Xlo[128][PST];
    __shared__ __align__(16) __nv_bfloat16 Whi[80][PST];
    __shared__ __align__(16) __nv_bfloat16 Wlo[80][PST];

    const int tid = threadIdx.x, w = tid >> 5, lane = tid & 31;
    const int wm = w >> 1, wn = w & 1;

    float acc[2][5][4];
#pragma unroll
    for (int mt = 0; mt < 2; ++mt)
#pragma unroll
        for (int nt = 0; nt < 5; ++nt)
#pragma unroll
            for (int j = 0; j < 4; ++j) acc[mt][nt][j] = 0.f;

    const uint32_t sxh = smem_u32(&Xhi[0][0]), sxl = smem_u32(&Xlo[0][0]);
    const uint32_t swh = smem_u32(&Whi[0][0]), swl = smem_u32(&Wlo[0][0]);

    for (int step = 0; step < KSTEPS; ++step) {
        const int k0 = step * 16;
        __syncthreads();
        for (int idx = tid; idx < 128 * 16; idx += 256) {
            const int r = idx >> 4, kk = idx & 15;
            const int k = k0 + kk;
            const float v = (k < PD) ? X[(size_t)(m0 + r) * PD + k] : 0.f;
            const __nv_bfloat16 h = __float2bfloat16_rn(v);
            Xhi[r][kk] = h;
            if (qpath) Xlo[r][kk] = __float2bfloat16_rn(v - __bfloat162float(h));
        }
        for (int idx = tid; idx < 80 * 16; idx += 256) {
            const int r = idx >> 4, kk = idx & 15;
            const int o = n0 + r, k = k0 + kk;
            const float v = (o < PD && k < PD) ? W[(size_t)o * PD + k] : 0.f;
            const __nv_bfloat16 h = __float2bfloat16_rn(v);
            Whi[r][kk] = h;
            if (qpath) Wlo[r][kk] = __float2bfloat16_rn(v - __bfloat162float(h));
        }
        __syncthreads();

        uint32_t ahi[2][4], alo[2][4];
        {
            const int r = lane & 15, ch = lane >> 4;
#pragma unroll
            for (int mt = 0; mt < 2; ++mt) {
                const uint32_t off = (uint32_t)(((wm * 32 + mt * 16 + r) * PST + ch * 8) * 2);
                LDSM4(ahi[mt], sxh + off);
                if (qpath) LDSM4(alo[mt], sxl + off);
            }
        }
        uint32_t bhi[5][2], blo[5][2];
        {
            const int sub = lane >> 3;
            const int nofs = (sub >> 1) * 8, kofs = (sub & 1) * 8;
#pragma unroll
            for (int p = 0; p < 2; ++p) {
                const int row = wn * 40 + p * 16 + nofs + (lane & 7);
                const uint32_t off = (uint32_t)((row * PST + kofs) * 2);
                uint32_t t[4];
                LDSM4(t, swh + off);
                bhi[2 * p][0] = t[0]; bhi[2 * p][1] = t[1];
                bhi[2 * p + 1][0] = t[2]; bhi[2 * p + 1][1] = t[3];
                if (qpath) {
                    LDSM4(t, swl + off);
                    blo[2 * p][0] = t[0]; blo[2 * p][1] = t[1];
                    blo[2 * p + 1][0] = t[2]; blo[2 * p + 1][1] = t[3];
                }
            }
            {
                const int row = wn * 40 + 32 + (lane & 7);
                const uint32_t off = (uint32_t)((row * PST + ((lane >> 3) & 1) * 8) * 2);
                LDSM2(bhi[4], swh + off);
                if (qpath) LDSM2(blo[4], swl + off);
            }
        }
        if (qpath) {
#pragma unroll
            for (int mt = 0; mt < 2; ++mt)
#pragma unroll
                for (int nt = 0; nt < 5; ++nt) {
                    MMA16816(acc[mt][nt], ahi[mt], bhi[nt][0], bhi[nt][1]);
                    MMA16816(acc[mt][nt], ahi[mt], blo[nt][0], blo[nt][1]);
                    MMA16816(acc[mt][nt], alo[mt], bhi[nt][0], bhi[nt][1]);
                }
        } else {
#pragma unroll
            for (int mt = 0; mt < 2; ++mt)
#pragma unroll
                for (int nt = 0; nt < 5; ++nt)
                    MMA16816(acc[mt][nt], ahi[mt], bhi[nt][0], bhi[nt][1]);
        }
    }

#pragma unroll
    for (int mt = 0; mt < 2; ++mt) {
        const int mbase = m0 + wm * 32 + mt * 16 + (lane >> 2);
#pragma unroll
        for (int nt = 0; nt < 5; ++nt) {
            const int obase = n0 + wn * 40 + nt * 8 + (lane & 3) * 2;
#pragma unroll
            for (int j = 0; j < 4; ++j) {
                const int m = mbase + (j >> 1) * 8;
                const int o = obase + (j & 1);
                if (o < PD) {
                    const float v = acc[mt][nt][j];
                    const int n = m >> 12, t = m & (PT - 1);
                    const int head = o / PDH, c = o - head * PDH;
                    const size_t idx = ((size_t)(head * PN + n) * PT + t) * 64 + c;
                    const __nv_bfloat16 h = __float2bfloat16_rn(v);
                    if (qpath) {
                        g_Qh[idx]  = h;
                        g_Qlo[idx] = __float2bfloat16_rn(v - __bfloat162float(h));
                    } else {
                        g_Kh[idx] = h;
                    }
                }
            }
        }
    }
}

// ---------------------------------------------------------------------------
// Kernel 2: approximate maxatt via warp-level bf16 HMMA. grid (16, 12, ZS=8).
// (R14 proven inner loop — untouched. Packing: launch_bounds(256,2).)
// ---------------------------------------------------------------------------
__global__ __launch_bounds__(256, 2) void scores_mma_kernel() {
    extern __shared__ __align__(16) __nv_bfloat16 smq[];
    const int tid = threadIdx.x, w = tid >> 5, lane = tid & 31;
    const int kt = blockIdx.x, b = blockIdx.y, z = blockIdx.z;
    const uint32_t sq = smem_u32(smq);

    const __nv_bfloat16* Ktp = g_Kh + ((size_t)b * PT + kt * KT) * 64;
    for (int i = tid; i < KT * 8; i += 256) {
        const int row = i >> 3, ch = i & 7;
        *reinterpret_cast<float4*>(&smq[row * RS + ch * 8]) =
            *reinterpret_cast<const float4*>(Ktp + row * 64 + ch * 8);
    }
    __syncthreads();

    uint32_t a[2][4][4];
    {
        const int r = lane & 15, ch = lane >> 4;
#pragma unroll
        for (int mt = 0; mt < 2; ++mt) {
            const uint32_t base = sq + (uint32_t)(((w * 32 + mt * 16 + r) * RS + ch * 8) * 2);
#pragma unroll
            for (int ks = 0; ks < 4; ++ks)
                LDSM4(a[mt][ks], base + ks * 32);
        }
    }
    __syncthreads();

    const __nv_bfloat16* Qbp = g_Qh + ((size_t)b * PT + (size_t)z * (PT / ZS)) * 64;
    const int NCH = (PT / ZS) / QCH;   // 4

    {
        const __nv_bfloat16* src = Qbp;
        for (int i = tid; i < QCH * 8; i += 256) {
            const int row = i >> 3, ch = i & 7;
            CP_ASYNC16(sq + (uint32_t)((row * RS + ch * 8) * 2), src + row * 64 + ch * 8);
        }
        CP_COMMIT();
    }

    float rm[2][2] = { { -3.0e38f, -3.0e38f }, { -3.0e38f, -3.0e38f } };

    for (int c = 0; c < NCH; ++c) {
        if (c + 1 < NCH) {
            const uint32_t dst0 = sq + (uint32_t)(((c + 1) & 1) * QCH * RS * 2);
            const __nv_bfloat16* src = Qbp + (size_t)(c + 1) * QCH * 64;
            for (int i = tid; i < QCH * 8; i += 256) {
                const int row = i >> 3, ch = i & 7;
                CP_ASYNC16(dst0 + (uint32_t)((row * RS + ch * 8) * 2), src + row * 64 + ch * 8);
            }
        }
        CP_COMMIT();
        CP_WAIT1();
        __syncthreads();

        const uint32_t qbase = sq + (uint32_t)((c & 1) * QCH * RS * 2);
#pragma unroll 4
        for (int nt = 0; nt < 16; ++nt) {
            const uint32_t baddr =
                qbase + (uint32_t)(((nt * 8 + (lane & 7)) * RS + (lane >> 3) * 8) * 2);
            uint32_t bf0[4], bf1[4];
            LDSM4(bf0, baddr);
            LDSM4(bf1, baddr + 64);
#pragma unroll
            for (int mt = 0; mt < 2; ++mt) {
                float d[4] = { 0.f, 0.f, 0.f, 0.f };
                MMA16816(d, a[mt][0], bf0[0], bf0[1]);
                MMA16816(d, a[mt][1], bf0[2], bf0[3]);
                MMA16816(d, a[mt][2], bf1[0], bf1[1]);
                MMA16816(d, a[mt][3], bf1[2], bf1[3]);
                rm[mt][0] = fmaxf(rm[mt][0], fmaxf(d[0], d[1]));
                rm[mt][1] = fmaxf(rm[mt][1], fmaxf(d[2], d[3]));
            }
        }
        __syncthreads();
    }

#pragma unroll
    for (int mt = 0; mt < 2; ++mt)
#pragma unroll
        for (int h = 0; h < 2; ++h) {
            rm[mt][h] = fmaxf(rm[mt][h], __shfl_xor_sync(0xffffffffu, rm[mt][h], 1));
            rm[mt][h] = fmaxf(rm[mt][h], __shfl_xor_sync(0xffffffffu, rm[mt][h], 2));
        }
    if ((lane & 3) == 0) {
        const size_t base = ((size_t)z * NB + b) * PT + kt * KT + w * 32;
#pragma unroll
        for (int mt = 0; mt < 2; ++mt) {
            g_maxapprox[base + mt * 16 + (lane >> 2)]     = rm[mt][0];
            g_maxapprox[base + mt * 16 + (lane >> 2) + 8] = rm[mt][1];
        }
    }
}

// ---------------------------------------------------------------------------
// Kernel 3a: per-slice bitonic sort (256 keys), emit slice top-64.
// grid (NB, 16) x 256. Folds ZS=8 partials.
// ---------------------------------------------------------------------------
__global__ __launch_bounds__(256) void cand_sortA_kernel() {
    const int b = blockIdx.x, sl = blockIdx.y, tid = threadIdx.x;
    __shared__ u64k key[256];

    const int i = sl * 256 + tid;
    float v = g_maxapprox[(size_t)b * PT + i];
#pragma unroll
    for (int zz = 1; zz < ZS; ++zz)
        v = fmaxf(v, g_maxapprox[((size_t)zz * NB + b) * PT + i]);
    key[tid] = ((u64k)orderable(v) << 32) | (uint32_t)(0xFFFFFFFFu - (uint32_t)i);
    __syncthreads();

#pragma unroll 1
    for (int k = 2; k <= 256; k <<= 1) {
#pragma unroll 1
        for (int j = k >> 1; j > 0; j >>= 1) {
            const int p = tid ^ j;
            const u64k mine = key[tid], other = key[p];
            const bool dirAsc = ((tid & k) != 0);
            const u64k nv = ((tid < p) == dirAsc)
                          ? (mine < other ? mine : other)
                          : (mine > other ? mine : other);
            __syncthreads();
            key[tid] = nv;
            __syncthreads();
        }
    }
    if (tid < 64) g_c1[(b * 16 + sl) * 64 + tid] = key[tid];
}

// ---------------------------------------------------------------------------
// Kernel 3b: bitonic sort of 1024 survivors; first 64 -> g_cand. grid NB x 1024.
// ---------------------------------------------------------------------------
__global__ __launch_bounds__(1024) void cand_sortB_kernel() {
    const int b = blockIdx.x, tid = threadIdx.x;
    __shared__ u64k key[1024];

    key[tid] = g_c1[b * 1024 + tid];
    __syncthreads();

#pragma unroll 1
    for (int k = 2; k <= 1024; k <<= 1) {
#pragma unroll 1
        for (int j = k >> 1; j > 0; j >>= 1) {
            const int p = tid ^ j;
            const u64k mine = key[tid], other = key[p];
            const bool dirAsc = ((tid & k) != 0);
            const u64k nv = ((tid < p) == dirAsc)
                          ? (mine < other ? mine : other)
                          : (mine > other ? mine : other);
            __syncthreads();
            key[tid] = nv;
            __syncthreads();
        }
    }
    if (tid < NCAND)
        g_cand[b * NCAND + tid] = (int)(0xFFFFFFFFu - (uint32_t)(key[tid] & 0xFFFFFFFFu));
}

// ---------------------------------------------------------------------------
// Kernel 3c: exact candidate-K gather-GEMM. grid (NB, 4) x 256; 16 cand/block.
// ---------------------------------------------------------------------------
__global__ __launch_bounds__(256) void kc_kernel(const float* __restrict__ keys,
                                                 const float* __restrict__ Wk) {
    const int b = blockIdx.x, g4 = blockIdx.y, tid = threadIdx.x;
    const int head = b / PN, n = b % PN;

    extern __shared__ __align__(16) float dsm[];
    float* sW    = dsm;              // [50][300]
    float* skeys = dsm + PDH * PD;   // [16][KCST]

    __shared__ int cid[16];
    if (tid < 16) cid[tid] = g_cand[b * NCAND + g4 * 16 + tid];
    __syncthreads();

    for (int i = tid; i < PDH * PD; i += 256)
        sW[i] = Wk[(size_t)(head * PDH) * PD + i];
    for (int i = tid; i < 16 * PD; i += 256) {
        const int c = i / PD, k = i - c * PD;
        skeys[c * KCST + k] = keys[((size_t)n * PT + cid[c]) * PD + k];
    }
    __syncthreads();

    const int c16 = tid & 15, jg = tid >> 4;
    float acc[4] = { 0.f, 0.f, 0.f, 0.f };

    for (int k = 0; k < PD; k += 4) {
        const float4 kv = *reinterpret_cast<const float4*>(&skeys[c16 * KCST + k]);
#pragma unroll
        for (int jj = 0; jj < 4; ++jj) {
            const int j = jg + 16 * jj;
            if (j < PDH) {
                const float4 wv4 = *reinterpret_cast<const float4*>(&sW[j * PD + k]);
                acc[jj] += kv.x * wv4.x + kv.y * wv4.y + kv.z * wv4.z + kv.w * wv4.w;
            }
        }
    }
#pragma unroll
    for (int jj = 0; jj < 4; ++jj) {
        const int j = jg + 16 * jj;
        if (j < PDH) g_Kc[(size_t)(b * NCAND + g4 * 16 + c16) * 52 + j] = acc[jj];
    }
}

// ---------------------------------------------------------------------------
// Kernel 4: per-candidate max over one 256-q chunk via bf16x3 HMMA
// (hi*hi + hi*lo + lo*hi). grid (NB, NQC=16) x 256.
// ---------------------------------------------------------------------------
__global__ __launch_bounds__(256, 1) void rescue_mma_kernel() {
    extern __shared__ __align__(16) __nv_bfloat16 rsm[];
    __nv_bfloat16* skhi = rsm;                       // [64][RS]
    __nv_bfloat16* sklo = rsm + 64 * RS;
    __nv_bfloat16* sqhi = rsm + 2 * 64 * RS;         // [256][RS]
    __nv_bfloat16* sqlo = rsm + 2 * 64 * RS + 256 * RS;

    __shared__ float sm_part[NCAND][8];

    const int b = blockIdx.x, qc = blockIdx.y;
    const int tid = threadIdx.x, w = tid >> 5, lane = tid & 31;
    const int q0 = qc * 256;

    for (int i = tid; i < 64 * 64; i += 256) {
        const int row = i >> 6, col = i & 63;
        const float v = (col < PDH) ? g_Kc[(size_t)(b * NCAND + row) * 52 + col] : 0.f;
        const __nv_bfloat16 h = __float2bfloat16_rn(v);
        skhi[row * RS + col] = h;
        sklo[row * RS + col] = __float2bfloat16_rn(v - __bfloat162float(h));
    }
    {
        const __nv_bfloat16* qh = g_Qh  + ((size_t)b * PT + q0) * 64;
        const __nv_bfloat16* ql = g_Qlo + ((size_t)b * PT + q0) * 64;
        for (int i = tid; i < 256 * 8; i += 256) {
            const int row = i >> 3, ch = i & 7;
            *reinterpret_cast<float4*>(&sqhi[row * RS + ch * 8]) =
                *reinterpret_cast<const float4*>(qh + row * 64 + ch * 8);
            *reinterpret_cast<float4*>(&sqlo[row * RS + ch * 8]) =
                *reinterpret_cast<const float4*>(ql + row * 64 + ch * 8);
        }
    }
    __syncthreads();

    const uint32_t skh = smem_u32(skhi), skl = smem_u32(sklo);
    const uint32_t sqh = smem_u32(sqhi), sql = smem_u32(sqlo);

    float rm[4][2];
#pragma unroll
    for (int mt = 0; mt < 4; ++mt) { rm[mt][0] = -3.0e38f; rm[mt][1] = -3.0e38f; }

#pragma unroll 1
    for (int mt = 0; mt < 4; ++mt) {
        uint32_t ahi[4][4], alo[4][4];
        {
            const int r = lane & 15, ch = lane >> 4;
            const uint32_t off = (uint32_t)(((mt * 16 + r) * RS + ch * 8) * 2);
#pragma unroll
            for (int ks = 0; ks < 4; ++ks) {
                LDSM4(ahi[ks], skh + off + ks * 32);
                LDSM4(alo[ks], skl + off + ks * 32);
            }
        }
#pragma unroll
        for (int nt = 0; nt < 4; ++nt) {
            const uint32_t boff =
                (uint32_t)(((w * 32 + nt * 8 + (lane & 7)) * RS + (lane >> 3) * 8) * 2);
            uint32_t bh0[4], bh1[4], bl0[4], bl1[4];
            LDSM4(bh0, sqh + boff);
            LDSM4(bh1, sqh + boff + 64);
            LDSM4(bl0, sql + boff);
            LDSM4(bl1, sql + boff + 64);

            float d[4] = { 0.f, 0.f, 0.f, 0.f };
            MMA16816(d, ahi[0], bh0[0], bh0[1]);
            MMA16816(d, ahi[1], bh0[2], bh0[3]);
            MMA16816(d, ahi[2], bh1[0], bh1[1]);
            MMA16816(d, ahi[3], bh1[2], bh1[3]);
            MMA16816(d, ahi[0], bl0[0], bl0[1]);
            MMA16816(d, ahi[1], bl0[2], bl0[3]);
            MMA16816(d, ahi[2], bl1[0], bl1[1]);
            MMA16816(d, ahi[3], bl1[2], bl1[3]);
            MMA16816(d, alo[0], bh0[0], bh0[1]);
            MMA16816(d, alo[1], bh0[2], bh0[3]);
            MMA16816(d, alo[2], bh1[0], bh1[1]);
            MMA16816(d, alo[3], bh1[2], bh1[3]);

            rm[mt][0] = fmaxf(rm[mt][0], fmaxf(d[0], d[1]));
            rm[mt][1] = fmaxf(rm[mt][1], fmaxf(d[2], d[3]));
        }
    }

#pragma unroll
    for (int mt = 0; mt < 4; ++mt)
#pragma unroll
        for (int h = 0; h < 2; ++h) {
            rm[mt][h] = fmaxf(rm[mt][h], __shfl_xor_sync(0xffffffffu, rm[mt][h], 1));
            rm[mt][h] = fmaxf(rm[mt][h], __shfl_xor_sync(0xffffffffu, rm[mt][h], 2));
        }
    if ((lane & 3) == 0) {
        const int r0 = lane >> 2;
#pragma unroll
        for (int mt = 0; mt < 4; ++mt) {
            sm_part[mt * 16 + r0][w]     = rm[mt][0];
            sm_part[mt * 16 + 8 + r0][w] = rm[mt][1];
        }
    }
    __syncthreads();
    if (tid < NCAND) {
        float m = sm_part[tid][0];
#pragma unroll
        for (int ww = 1; ww < 8; ++ww) m = fmaxf(m, sm_part[tid][ww]);
        g_exactpart[(size_t)(b * NQC + qc) * NCAND + tid] = m;
    }
}

// ---------------------------------------------------------------------------
// Kernel 5: fold chunks, single-pass rank top-20 (value desc, tie -> lowest
// global index), softmax, gather from g_Kc. grid 12 x 64.
// ---------------------------------------------------------------------------
__global__ __launch_bounds__(64) void final_kernel(float* __restrict__ out) {
    const int b = blockIdx.x;
    const int head = b / PN, n = b % PN;
    const int tid = threadIdx.x;

    __shared__ u64k  keys_s[NCAND];
    __shared__ float topv[PTOPK];
    __shared__ int   topslot[PTOPK];
    __shared__ float probs[PTOPK];

    const int ci = g_cand[b * NCAND + tid];
    float e = -3.0e38f;
    for (int s = 0; s < NQC; ++s)
        e = fmaxf(e, g_exactpart[(size_t)(b * NQC + s) * NCAND + tid]);

    const u64k mine = ((u64k)orderable(e) << 32) | (uint32_t)(0xFFFFFFFFu - (uint32_t)ci);
    keys_s[tid] = mine;
    __syncthreads();

    int rank = 0;
#pragma unroll
    for (int j = 0; j < NCAND; ++j)
        rank += (keys_s[j] > mine);

    if (rank < PTOPK) { topv[rank] = e; topslot[rank] = tid; }
    __syncthreads();

    if (tid == 0) {
        const float inv = rsqrtf((float)PDH);
        float s = 0.f, ex[PTOPK];
#pragma unroll
        for (int i = 0; i < PTOPK; ++i) { ex[i] = expf((topv[i] - topv[0]) * inv); s += ex[i]; }
        const float invs = 1.0f / s;
#pragma unroll
        for (int i = 0; i < PTOPK; ++i) probs[i] = ex[i] * invs;
    }
    __syncthreads();

    for (int j = tid; j < PDH; j += 64) {
        float acc = 0.f;
#pragma unroll
        for (int i = 0; i < PTOPK; ++i)
            acc += probs[i] * g_Kc[(size_t)(b * NCAND + topslot[i]) * 52 + j];
        out[(size_t)n * PD + head * PDH + j] = acc;
    }
}

// ---------------------------------------------------------------------------
extern "C" void kernel_launch(void* const* d_in, const int* in_sizes, int n_in,
                              void* d_out, int out_size) {
    const float* querys = (const float*)d_in[0];
    const float* keys   = (const float*)d_in[1];
    const float* Wq     = (const float*)d_in[3];
    const float* Wk     = (const float*)d_in[4];

    dim3 gproj(PN * PT / 128, 4, 2);
    proj_kernel<<<gproj, 256>>>(querys, keys, Wq, Wk);

    const int scsmem = 2 * QCH * RS * 2;   // 36864 B
    dim3 gsc(PT / KT, NB, ZS);
    scores_mma_kernel<<<gsc, 256, scsmem>>>();

    cand_sortA_kernel<<<dim3(NB, 16), 256>>>();
    cand_sortB_kernel<<<NB, 1024>>>();

    const int kcsmem = (PDH * PD + 16 * KCST) * (int)sizeof(float);   // 79712 B
    cudaFuncSetAttribute(kc_kernel, cudaFuncAttributeMaxDynamicSharedMemorySize, kcsmem);
    kc_kernel<<<dim3(NB, 4), 256, kcsmem>>>(keys, Wk);

    const int rsmem = (2 * 64 * RS + 2 * 256 * RS) * 2;   // 92160 B
    cudaFuncSetAttribute(rescue_mma_kernel, cudaFuncAttributeMaxDynamicSharedMemorySize, rsmem);
    rescue_mma_kernel<<<dim3(NB, NQC), 256, rsmem>>>();

    final_kernel<<<NB, NCAND>>>((float*)d_out);
}